// round 1
// baseline (speedup 1.0000x reference)
#include <cuda_runtime.h>
#include <math.h>

// Problem constants
#define Bb   4
#define Ss   1024
#define Hh   16
#define Dd   64
#define HID  1024
#define BH   (Bb*Hh)       // 64
#define RR   181
#define RP   192           // padded bucket count

// -------- scratch (device globals; no runtime allocation) --------
__device__ float g_Q [(size_t)BH * Ss * Dd];          // [B,H,S,D] 16MB
__device__ float g_K [(size_t)BH * Ss * Dd];
__device__ float g_V [(size_t)BH * Ss * Dd];
__device__ float g_RS[(size_t)BH * Ss * RP];          // rel scores  50MB
__device__ float g_BS[(size_t)BH * Ss * RP];          // bucket sums 50MB
__device__ float g_P [(size_t)BH * Ss * Ss];          // energy/attn 256MB
__device__ float g_X [(size_t)Bb * Ss * HID];         // x + r_x     16MB

// ============================================================
// SGEMM: C[M,N] = A[M,K] @ W[N,K]^T + bias ; M=4096,N=K=1024
// out_mode 0: row-major [M,N]; out_mode 1: write [B,H,S,D]
// a_sel 1 -> A = g_X ; out_sel 0/1/2 -> g_Q/g_K/g_V, else Cout
// ============================================================
__global__ __launch_bounds__(256) void sgemm_bias(
    const float* __restrict__ Ain, const float* __restrict__ W,
    const float* __restrict__ bias, float* __restrict__ Cout,
    int a_sel, int out_sel, int out_mode)
{
    const int M = Bb * Ss, N = HID, K = HID;
    __shared__ float As[16][128];
    __shared__ float Bs[16][128];
    const float* A = (a_sel == 1) ? g_X : Ain;
    float* C = (out_sel == 0) ? g_Q : (out_sel == 1) ? g_K : (out_sel == 2) ? g_V : Cout;

    const int tid = threadIdx.x;
    const int tx = tid & 15, ty = tid >> 4;
    const int bm = blockIdx.y * 128, bn = blockIdx.x * 128;
    const int a_r = tid >> 2;              // 0..63
    const int a_c = (tid & 3) << 2;        // 0,4,8,12

    float acc[8][8];
    #pragma unroll
    for (int i = 0; i < 8; i++)
        #pragma unroll
        for (int j = 0; j < 8; j++) acc[i][j] = 0.f;

    for (int k0 = 0; k0 < K; k0 += 16) {
        #pragma unroll
        for (int i = 0; i < 2; i++) {
            float4 va = *(const float4*)(A + (size_t)(bm + a_r + i*64) * K + k0 + a_c);
            As[a_c+0][a_r + i*64] = va.x;
            As[a_c+1][a_r + i*64] = va.y;
            As[a_c+2][a_r + i*64] = va.z;
            As[a_c+3][a_r + i*64] = va.w;
            float4 vb = *(const float4*)(W + (size_t)(bn + a_r + i*64) * K + k0 + a_c);
            Bs[a_c+0][a_r + i*64] = vb.x;
            Bs[a_c+1][a_r + i*64] = vb.y;
            Bs[a_c+2][a_r + i*64] = vb.z;
            Bs[a_c+3][a_r + i*64] = vb.w;
        }
        __syncthreads();
        #pragma unroll
        for (int kk = 0; kk < 16; kk++) {
            float af[8], bf[8];
            *(float4*)&af[0] = *(const float4*)&As[kk][ty*8];
            *(float4*)&af[4] = *(const float4*)&As[kk][ty*8+4];
            *(float4*)&bf[0] = *(const float4*)&Bs[kk][tx*8];
            *(float4*)&bf[4] = *(const float4*)&Bs[kk][tx*8+4];
            #pragma unroll
            for (int i = 0; i < 8; i++)
                #pragma unroll
                for (int j = 0; j < 8; j++)
                    acc[i][j] += af[i] * bf[j];
        }
        __syncthreads();
    }
    #pragma unroll
    for (int i = 0; i < 8; i++) {
        int m = bm + ty*8 + i;
        #pragma unroll
        for (int j = 0; j < 8; j++) {
            int n = bn + tx*8 + j;
            float v = acc[i][j] + bias[n];
            if (out_mode == 0) {
                C[(size_t)m * N + n] = v;
            } else {
                int b = m >> 10, s = m & 1023, h = n >> 6, d = n & 63;
                C[(((size_t)(b*Hh + h) * Ss) + s) * Dd + d] = v;
            }
        }
    }
}

// ============================================================
// RS[b,h,q,r] = sum_d Q[b,h,q,d] * rel_k_emb[r,d]
// ============================================================
__global__ __launch_bounds__(256) void rel_scores_kernel(const float* __restrict__ rk)
{
    extern __shared__ float sm[];
    float (*Qs)[65]  = (float(*)[65])sm;             // 64 x 65
    float (*rkT)[RP] = (float(*)[RP])(sm + 64*65);   // [d][r]
    int bh = blockIdx.y, q0 = blockIdx.x * 64;
    int tid = threadIdx.x;
    const float* Qb = g_Q + ((size_t)bh * Ss + q0) * Dd;
    for (int idx = tid; idx < 64*16; idx += 256) {
        int r = idx >> 4, c4 = (idx & 15) * 4;
        float4 v = *(const float4*)(Qb + (size_t)r * Dd + c4);
        Qs[r][c4] = v.x; Qs[r][c4+1] = v.y; Qs[r][c4+2] = v.z; Qs[r][c4+3] = v.w;
    }
    for (int idx = tid; idx < RR*64; idx += 256) {
        int r = idx >> 6, d = idx & 63;
        rkT[d][r] = rk[idx];
    }
    __syncthreads();
    int tx = tid & 15, ty = tid >> 4;
    float acc[4][12];
    #pragma unroll
    for (int i = 0; i < 4; i++)
        #pragma unroll
        for (int j = 0; j < 12; j++) acc[i][j] = 0.f;
    for (int d = 0; d < 64; d++) {
        float af[4];
        #pragma unroll
        for (int i = 0; i < 4; i++) af[i] = Qs[ty + 16*i][d];
        #pragma unroll
        for (int j = 0; j < 12; j++) {
            int r = tx + 16*j;
            float bv = (r < RR) ? rkT[d][r] : 0.f;
            #pragma unroll
            for (int i = 0; i < 4; i++) acc[i][j] += af[i] * bv;
        }
    }
    float* out = g_RS + ((size_t)bh * Ss + q0) * RP;
    #pragma unroll
    for (int i = 0; i < 4; i++)
        #pragma unroll
        for (int j = 0; j < 12; j++) {
            int r = tx + 16*j, q = ty + 16*i;
            if (r < RR) out[(size_t)q * RP + r] = acc[i][j];
        }
}

// ============================================================
// energy[bh,q,k] = (Q.K + abs[h,q,k] + RS[bh,q,clip(k-q)+90]) / 8 ; mask
// tile 128x128, K=64 single shot
// ============================================================
__global__ __launch_bounds__(256) void energy_kernel(
    const float* __restrict__ abse, const int* __restrict__ mask)
{
    extern __shared__ float sm[];
    float (*Qs)[65] = (float(*)[65])sm;             // 128 x 65
    float (*Ks)[65] = (float(*)[65])(sm + 128*65);
    int kt = blockIdx.x, qt = blockIdx.y, bh = blockIdx.z;
    int q0 = qt * 128, k0 = kt * 128;
    int tid = threadIdx.x, tx = tid & 15, ty = tid >> 4;
    const float* Qb = g_Q + ((size_t)bh * Ss + q0) * Dd;
    const float* Kb = g_K + ((size_t)bh * Ss + k0) * Dd;
    for (int idx = tid; idx < 128*16; idx += 256) {
        int r = idx >> 4, c4 = (idx & 15) * 4;
        float4 v = *(const float4*)(Qb + (size_t)r * Dd + c4);
        Qs[r][c4] = v.x; Qs[r][c4+1] = v.y; Qs[r][c4+2] = v.z; Qs[r][c4+3] = v.w;
        float4 w = *(const float4*)(Kb + (size_t)r * Dd + c4);
        Ks[r][c4] = w.x; Ks[r][c4+1] = w.y; Ks[r][c4+2] = w.z; Ks[r][c4+3] = w.w;
    }
    __syncthreads();
    float acc[8][8];
    #pragma unroll
    for (int i = 0; i < 8; i++)
        #pragma unroll
        for (int j = 0; j < 8; j++) acc[i][j] = 0.f;
    for (int d = 0; d < 64; d++) {
        float af[8], bf[8];
        #pragma unroll
        for (int i = 0; i < 8; i++) af[i] = Qs[ty + 16*i][d];
        #pragma unroll
        for (int j = 0; j < 8; j++) bf[j] = Ks[tx + 16*j][d];
        #pragma unroll
        for (int i = 0; i < 8; i++)
            #pragma unroll
            for (int j = 0; j < 8; j++)
                acc[i][j] += af[i] * bf[j];
    }
    int b = bh >> 4, h = bh & 15;
    const float* RSb = g_RS + (size_t)bh * Ss * RP;
    #pragma unroll
    for (int i = 0; i < 8; i++) {
        int q = q0 + ty + 16*i;
        #pragma unroll
        for (int j = 0; j < 8; j++) {
            int k = k0 + tx + 16*j;
            int delta = k - q;
            int ridx = min(max(delta, -90), 90) + 90;
            float e = (acc[i][j]
                       + abse[((size_t)h * Ss + q) * Ss + k]
                       + RSb[(size_t)q * RP + ridx]) * 0.125f;
            if (mask[((size_t)b * Ss + q) * Ss + k] == 0) e = -1e10f;
            g_P[((size_t)bh * Ss + q) * Ss + k] = e;
        }
    }
}

// ============================================================
// softmax over last dim (1024), in place on g_P
// ============================================================
__global__ __launch_bounds__(256) void softmax_kernel()
{
    __shared__ float redm[8];
    __shared__ float reds[8];
    int q = blockIdx.x, bh = blockIdx.y;
    float* p = g_P + ((size_t)bh * Ss + q) * Ss;
    int tid = threadIdx.x;
    float4 v = ((float4*)p)[tid];
    float m = fmaxf(fmaxf(v.x, v.y), fmaxf(v.z, v.w));
    #pragma unroll
    for (int o = 16; o; o >>= 1) m = fmaxf(m, __shfl_xor_sync(0xffffffffu, m, o));
    if ((tid & 31) == 0) redm[tid >> 5] = m;
    __syncthreads();
    m = redm[0];
    #pragma unroll
    for (int w = 1; w < 8; w++) m = fmaxf(m, redm[w]);
    float ex = __expf(v.x - m), ey = __expf(v.y - m);
    float ez = __expf(v.z - m), ew = __expf(v.w - m);
    float s = ex + ey + ez + ew;
    #pragma unroll
    for (int o = 16; o; o >>= 1) s += __shfl_xor_sync(0xffffffffu, s, o);
    if ((tid & 31) == 0) reds[tid >> 5] = s;
    __syncthreads();
    s = reds[0];
    #pragma unroll
    for (int w = 1; w < 8; w++) s += reds[w];
    float inv = 1.0f / s;
    ((float4*)p)[tid] = make_float4(ex*inv, ey*inv, ez*inv, ew*inv);
}

// ============================================================
// x[b,q,h,d] = sum_k attn[bh,q,k] * V[bh,k,d]   -> g_X [B,S,HID]
// ============================================================
__global__ __launch_bounds__(256) void xattn_kernel()
{
    extern __shared__ float sm[];
    float (*Ps)[65] = (float(*)[65])sm;             // 128 x 65
    float (*Vs)[65] = (float(*)[65])(sm + 128*65);  // 64 x 65
    int bh = blockIdx.y, q0 = blockIdx.x * 128;
    int tid = threadIdx.x, tx = tid & 15, ty = tid >> 4;
    const float* Pb = g_P + ((size_t)bh * Ss + q0) * Ss;
    const float* Vb = g_V + (size_t)bh * Ss * Dd;
    float acc[8][4];
    #pragma unroll
    for (int i = 0; i < 8; i++)
        #pragma unroll
        for (int j = 0; j < 4; j++) acc[i][j] = 0.f;

    for (int k0 = 0; k0 < Ss; k0 += 64) {
        for (int idx = tid; idx < 128*16; idx += 256) {
            int qq = idx >> 4, c4 = (idx & 15) * 4;
            float4 v = *(const float4*)(Pb + (size_t)qq * Ss + k0 + c4);
            Ps[qq][c4] = v.x; Ps[qq][c4+1] = v.y; Ps[qq][c4+2] = v.z; Ps[qq][c4+3] = v.w;
        }
        for (int idx = tid; idx < 64*16; idx += 256) {
            int kk = idx >> 4, c4 = (idx & 15) * 4;
            float4 v = *(const float4*)(Vb + (size_t)(k0 + kk) * Dd + c4);
            Vs[kk][c4] = v.x; Vs[kk][c4+1] = v.y; Vs[kk][c4+2] = v.z; Vs[kk][c4+3] = v.w;
        }
        __syncthreads();
        for (int kk = 0; kk < 64; kk++) {
            float af[8], bf[4];
            #pragma unroll
            for (int i = 0; i < 8; i++) af[i] = Ps[ty + 16*i][kk];
            #pragma unroll
            for (int j = 0; j < 4; j++) bf[j] = Vs[kk][tx + 16*j];
            #pragma unroll
            for (int i = 0; i < 8; i++)
                #pragma unroll
                for (int j = 0; j < 4; j++)
                    acc[i][j] += af[i] * bf[j];
        }
        __syncthreads();
    }
    int b = bh >> 4, h = bh & 15;
    #pragma unroll
    for (int i = 0; i < 8; i++) {
        int q = q0 + ty + 16*i;
        #pragma unroll
        for (int j = 0; j < 4; j++) {
            int d = tx + 16*j;
            g_X[((size_t)(b*Ss + q)) * HID + h*Dd + d] = acc[i][j];
        }
    }
}

// ============================================================
// bucket sums: BS[bh,q,0]=sum_{k<=q-90} attn, BS[..,180]=sum_{k>=q+90},
// BS[..,r]=attn[q, q+r-90] for 1..179 ; padding zeroed
// ============================================================
__global__ __launch_bounds__(256) void buckets_kernel()
{
    __shared__ float r0s[8];
    __shared__ float r1s[8];
    int q = blockIdx.x, bh = blockIdx.y;
    const float* p = g_P + ((size_t)bh * Ss + q) * Ss;
    float* out = g_BS + ((size_t)bh * Ss + q) * RP;
    int tid = threadIdx.x;
    float t0 = 0.f, t1 = 0.f;
    for (int k = tid; k <= q - 90; k += 256) t0 += p[k];
    for (int k = q + 90 + tid; k < Ss; k += 256) t1 += p[k];
    #pragma unroll
    for (int o = 16; o; o >>= 1) {
        t0 += __shfl_xor_sync(0xffffffffu, t0, o);
        t1 += __shfl_xor_sync(0xffffffffu, t1, o);
    }
    if ((tid & 31) == 0) { r0s[tid >> 5] = t0; r1s[tid >> 5] = t1; }
    __syncthreads();
    float T0 = 0.f, T1 = 0.f;
    #pragma unroll
    for (int w = 0; w < 8; w++) { T0 += r0s[w]; T1 += r1s[w]; }
    if (tid < RP) {
        float val = 0.f;
        if (tid == 0) val = T0;
        else if (tid == 180) val = T1;
        else if (tid < 180) {
            int k = q + tid - 90;
            if (k >= 0 && k < Ss) val = p[k];
        }
        out[tid] = val;
    }
}

// ============================================================
// g_X[b,q,h,d] += BS[bh,q,:] @ rel_v_emb[:,d]
// ============================================================
__global__ __launch_bounds__(256) void rx_add_kernel(const float* __restrict__ rv)
{
    extern __shared__ float sm[];
    float (*BSs)[193] = (float(*)[193])sm;            // 64 x 193
    float (*rvs)[64]  = (float(*)[64])(sm + 64*193);  // 181 x 64
    int bh = blockIdx.y, q0 = blockIdx.x * 64;
    int tid = threadIdx.x, tx = tid & 15, ty = tid >> 4;
    const float* BSb = g_BS + ((size_t)bh * Ss + q0) * RP;
    for (int idx = tid; idx < 64*RP; idx += 256) {
        int q = idx / RP, r = idx % RP;
        BSs[q][r] = BSb[idx];
    }
    for (int idx = tid; idx < RR*64; idx += 256) {
        int r = idx >> 6, d = idx & 63;
        rvs[r][d] = rv[idx];
    }
    __syncthreads();
    float acc[4][4];
    #pragma unroll
    for (int i = 0; i < 4; i++)
        #pragma unroll
        for (int j = 0; j < 4; j++) acc[i][j] = 0.f;
    for (int r = 0; r < RR; r++) {
        float af[4], bf[4];
        #pragma unroll
        for (int i = 0; i < 4; i++) af[i] = BSs[ty + 16*i][r];
        #pragma unroll
        for (int j = 0; j < 4; j++) bf[j] = rvs[r][tx + 16*j];
        #pragma unroll
        for (int i = 0; i < 4; i++)
            #pragma unroll
            for (int j = 0; j < 4; j++)
                acc[i][j] += af[i] * bf[j];
    }
    int b = bh >> 4, h = bh & 15;
    #pragma unroll
    for (int i = 0; i < 4; i++) {
        int q = q0 + ty + 16*i;
        #pragma unroll
        for (int j = 0; j < 4; j++) {
            int d = tx + 16*j;
            size_t o = ((size_t)(b*Ss + q)) * HID + h*Dd + d;
            g_X[o] += acc[i][j];
        }
    }
}

// ============================================================
extern "C" void kernel_launch(void* const* d_in, const int* in_sizes, int n_in,
                              void* d_out, int out_size)
{
    const float* query = (const float*)d_in[0];
    const float* key   = (const float*)d_in[1];
    const float* value = (const float*)d_in[2];
    const int*   mask  = (const int*)  d_in[3];
    const float* abse  = (const float*)d_in[4];
    const float* Wq    = (const float*)d_in[5];
    const float* bq    = (const float*)d_in[6];
    const float* Wk    = (const float*)d_in[7];
    const float* bk    = (const float*)d_in[8];
    const float* Wv    = (const float*)d_in[9];
    const float* bv    = (const float*)d_in[10];
    const float* Wo    = (const float*)d_in[11];
    const float* bo    = (const float*)d_in[12];
    const float* rk    = (const float*)d_in[13];
    const float* rv    = (const float*)d_in[14];
    float* out = (float*)d_out;

    const int smem_rel  = (64*65 + 64*RP) * 4;
    const int smem_en   = (128*65 * 2) * 4;
    const int smem_xat  = (128*65 + 64*65) * 4;
    const int smem_rx   = (64*193 + RR*64) * 4;
    cudaFuncSetAttribute(rel_scores_kernel, cudaFuncAttributeMaxDynamicSharedMemorySize, smem_rel);
    cudaFuncSetAttribute(energy_kernel,     cudaFuncAttributeMaxDynamicSharedMemorySize, smem_en);
    cudaFuncSetAttribute(xattn_kernel,      cudaFuncAttributeMaxDynamicSharedMemorySize, smem_xat);
    cudaFuncSetAttribute(rx_add_kernel,     cudaFuncAttributeMaxDynamicSharedMemorySize, smem_rx);

    dim3 gProj(HID/128, (Bb*Ss)/128);
    sgemm_bias<<<gProj, 256>>>(query, Wq, bq, nullptr, 0, 0, 1);
    sgemm_bias<<<gProj, 256>>>(key,   Wk, bk, nullptr, 0, 1, 1);
    sgemm_bias<<<gProj, 256>>>(value, Wv, bv, nullptr, 0, 2, 1);

    rel_scores_kernel<<<dim3(Ss/64, BH), 256, smem_rel>>>(rk);
    energy_kernel<<<dim3(Ss/128, Ss/128, BH), 256, smem_en>>>(abse, mask);
    softmax_kernel<<<dim3(Ss, BH), 256>>>();
    xattn_kernel<<<dim3(Ss/128, BH), 256, smem_xat>>>();
    buckets_kernel<<<dim3(Ss, BH), 256>>>();
    rx_add_kernel<<<dim3(Ss/64, BH), 256, smem_rx>>>(rv);

    sgemm_bias<<<gProj, 256>>>(nullptr, Wo, bo, out, 1, -1, 0);
}

// round 2
// speedup vs baseline: 1.8192x; 1.8192x over previous
#include <cuda_runtime.h>
#include <math.h>
#include <stdint.h>

// Problem constants
#define Bb   4
#define Ss   1024
#define Hh   16
#define Dd   64
#define HID  1024
#define BH   (Bb*Hh)       // 64
#define RR   181
#define RP   192           // padded bucket count

// -------- scratch (device globals; no runtime allocation) --------
__device__ float g_Q [(size_t)BH * Ss * Dd];
__device__ float g_K [(size_t)BH * Ss * Dd];
__device__ float g_V [(size_t)BH * Ss * Dd];
__device__ float g_RS[(size_t)BH * Ss * RP];
__device__ float g_BS[(size_t)BH * Ss * RP];
__device__ float g_P [(size_t)BH * Ss * Ss];
__device__ float g_X [(size_t)Bb * Ss * HID];

// ---------------- tf32 mma helpers ----------------
__device__ __forceinline__ uint32_t cvt_tf32(float x) {
    uint32_t r; asm("cvt.rna.tf32.f32 %0, %1;" : "=r"(r) : "f"(x)); return r;
}
__device__ __forceinline__ float cvtf_tf32(float x) {
    return __uint_as_float(cvt_tf32(x));
}
__device__ __forceinline__ void mma_tf32(float c[4], const uint32_t a[4], const uint32_t b[2]) {
    asm volatile(
        "mma.sync.aligned.m16n8k8.row.col.f32.tf32.tf32.f32 "
        "{%0,%1,%2,%3}, {%4,%5,%6,%7}, {%8,%9}, {%0,%1,%2,%3};"
        : "+f"(c[0]), "+f"(c[1]), "+f"(c[2]), "+f"(c[3])
        : "r"(a[0]), "r"(a[1]), "r"(a[2]), "r"(a[3]), "r"(b[0]), "r"(b[1]));
}

// ============================================================
// Tensor-core SGEMM: C[M,N] = A[M,K] @ W[N,K]^T + bias
// M=4096, N=K=1024. Block 128x128, BK=32, 8 warps (warp 64x32).
// out_mode 0: row-major [M,N]; out_mode 1: write [B,H,S,D]
// ============================================================
__global__ __launch_bounds__(256) void sgemm_bias_tc(
    const float* __restrict__ Ain, const float* __restrict__ W,
    const float* __restrict__ bias, float* __restrict__ Cout,
    int a_sel, int out_sel, int out_mode)
{
    const int K = HID, N = HID;
    __shared__ float As[32][136];   // [k][m], stride 136 (conflict-free frag loads)
    __shared__ float Bs[32][136];   // [k][n]
    const float* A = (a_sel == 1) ? g_X : Ain;
    float* C = (out_sel == 0) ? g_Q : (out_sel == 1) ? g_K : (out_sel == 2) ? g_V : Cout;

    const int tid = threadIdx.x, lane = tid & 31, wid = tid >> 5;
    const int gidq = lane >> 2, tig = lane & 3;
    const int warp_m = (wid & 1) * 64, warp_n = (wid >> 1) * 32;
    const int bm = blockIdx.y * 128, bn = blockIdx.x * 128;
    const int srow = tid & 31;
    const int scol = (tid >> 5) * 4;

    float acc[4][4][4];
    #pragma unroll
    for (int i = 0; i < 4; i++)
        #pragma unroll
        for (int j = 0; j < 4; j++)
            #pragma unroll
            for (int r = 0; r < 4; r++) acc[i][j][r] = 0.f;

    for (int k0 = 0; k0 < K; k0 += 32) {
        #pragma unroll
        for (int i = 0; i < 4; i++) {
            int ml = srow + 32 * i;
            float4 va = *(const float4*)(A + (size_t)(bm + ml) * K + k0 + scol);
            As[scol+0][ml] = cvtf_tf32(va.x);
            As[scol+1][ml] = cvtf_tf32(va.y);
            As[scol+2][ml] = cvtf_tf32(va.z);
            As[scol+3][ml] = cvtf_tf32(va.w);
            float4 vb = *(const float4*)(W + (size_t)(bn + ml) * K + k0 + scol);
            Bs[scol+0][ml] = cvtf_tf32(vb.x);
            Bs[scol+1][ml] = cvtf_tf32(vb.y);
            Bs[scol+2][ml] = cvtf_tf32(vb.z);
            Bs[scol+3][ml] = cvtf_tf32(vb.w);
        }
        __syncthreads();
        #pragma unroll
        for (int kk = 0; kk < 32; kk += 8) {
            uint32_t af[4][4], bf[4][2];
            #pragma unroll
            for (int ma = 0; ma < 4; ma++) {
                int m = warp_m + 16 * ma + gidq;
                af[ma][0] = __float_as_uint(As[kk+tig  ][m]);
                af[ma][1] = __float_as_uint(As[kk+tig  ][m+8]);
                af[ma][2] = __float_as_uint(As[kk+tig+4][m]);
                af[ma][3] = __float_as_uint(As[kk+tig+4][m+8]);
            }
            #pragma unroll
            for (int nb = 0; nb < 4; nb++) {
                int n = warp_n + 8 * nb + gidq;
                bf[nb][0] = __float_as_uint(Bs[kk+tig  ][n]);
                bf[nb][1] = __float_as_uint(Bs[kk+tig+4][n]);
            }
            #pragma unroll
            for (int ma = 0; ma < 4; ma++)
                #pragma unroll
                for (int nb = 0; nb < 4; nb++)
                    mma_tf32(acc[ma][nb], af[ma], bf[nb]);
        }
        __syncthreads();
    }

    #pragma unroll
    for (int ma = 0; ma < 4; ma++) {
        int m0 = bm + warp_m + 16 * ma + gidq;
        #pragma unroll
        for (int nb = 0; nb < 4; nb++) {
            int n0 = bn + warp_n + 8 * nb + 2 * tig;
            float bx = bias[n0], by = bias[n0 + 1];
            #pragma unroll
            for (int half = 0; half < 2; half++) {
                int m = m0 + 8 * half;
                float vx = acc[ma][nb][2*half+0] + bx;
                float vy = acc[ma][nb][2*half+1] + by;
                if (out_mode == 0) {
                    float2 o = make_float2(vx, vy);
                    *(float2*)(C + (size_t)m * N + n0) = o;
                } else {
                    int b = m >> 10, s = m & 1023, h = n0 >> 6, d = n0 & 63;
                    float2 o = make_float2(vx, vy);
                    *(float2*)(C + (((size_t)(b*Hh + h) * Ss) + s) * Dd + d) = o;
                }
            }
        }
    }
}

// ============================================================
// RS[bh,q,r] = sum_d Q[bh,q,d] * rel_k_emb[r,d]   (tf32 mma)
// Block: 128 q rows x 192 r cols, K=64 (2 chunks of 32).
// 8 warps: warp 64x48 (4 m-atoms x 6 n-atoms).
// ============================================================
__global__ __launch_bounds__(256) void rel_scores_tc(const float* __restrict__ rk)
{
    __shared__ float As[32][136];   // [k][q]
    __shared__ float Bs[32][200];   // [k][r]
    int bh = blockIdx.y, q0 = blockIdx.x * 128;
    const int tid = threadIdx.x, lane = tid & 31, wid = tid >> 5;
    const int gidq = lane >> 2, tig = lane & 3;
    const int warp_m = (wid & 1) * 64, warp_n = (wid >> 1) * 48;
    const int srow = tid & 31, scol = (tid >> 5) * 4;
    const float* Qb = g_Q + ((size_t)bh * Ss + q0) * Dd;

    float acc[4][6][4];
    #pragma unroll
    for (int i = 0; i < 4; i++)
        #pragma unroll
        for (int j = 0; j < 6; j++)
            #pragma unroll
            for (int r = 0; r < 4; r++) acc[i][j][r] = 0.f;

    for (int k0 = 0; k0 < 64; k0 += 32) {
        #pragma unroll
        for (int i = 0; i < 4; i++) {
            int ml = srow + 32 * i;
            float4 va = *(const float4*)(Qb + (size_t)ml * Dd + k0 + scol);
            As[scol+0][ml] = cvtf_tf32(va.x);
            As[scol+1][ml] = cvtf_tf32(va.y);
            As[scol+2][ml] = cvtf_tf32(va.z);
            As[scol+3][ml] = cvtf_tf32(va.w);
        }
        #pragma unroll
        for (int i = 0; i < 6; i++) {
            int rl = srow + 32 * i;
            float4 vb = (rl < RR) ? *(const float4*)(rk + (size_t)rl * Dd + k0 + scol)
                                  : make_float4(0.f, 0.f, 0.f, 0.f);
            Bs[scol+0][rl] = cvtf_tf32(vb.x);
            Bs[scol+1][rl] = cvtf_tf32(vb.y);
            Bs[scol+2][rl] = cvtf_tf32(vb.z);
            Bs[scol+3][rl] = cvtf_tf32(vb.w);
        }
        __syncthreads();
        #pragma unroll
        for (int kk = 0; kk < 32; kk += 8) {
            uint32_t af[4][4], bf[6][2];
            #pragma unroll
            for (int ma = 0; ma < 4; ma++) {
                int m = warp_m + 16 * ma + gidq;
                af[ma][0] = __float_as_uint(As[kk+tig  ][m]);
                af[ma][1] = __float_as_uint(As[kk+tig  ][m+8]);
                af[ma][2] = __float_as_uint(As[kk+tig+4][m]);
                af[ma][3] = __float_as_uint(As[kk+tig+4][m+8]);
            }
            #pragma unroll
            for (int nb = 0; nb < 6; nb++) {
                int n = warp_n + 8 * nb + gidq;
                bf[nb][0] = __float_as_uint(Bs[kk+tig  ][n]);
                bf[nb][1] = __float_as_uint(Bs[kk+tig+4][n]);
            }
            #pragma unroll
            for (int ma = 0; ma < 4; ma++)
                #pragma unroll
                for (int nb = 0; nb < 6; nb++)
                    mma_tf32(acc[ma][nb], af[ma], bf[nb]);
        }
        __syncthreads();
    }

    float* out = g_RS + ((size_t)bh * Ss + q0) * RP;
    #pragma unroll
    for (int ma = 0; ma < 4; ma++) {
        int qm = warp_m + 16 * ma + gidq;
        #pragma unroll
        for (int nb = 0; nb < 6; nb++) {
            int r0 = warp_n + 8 * nb + 2 * tig;
            #pragma unroll
            for (int half = 0; half < 2; half++) {
                int q = qm + 8 * half;
                if (r0 < RR)     out[(size_t)q * RP + r0]     = acc[ma][nb][2*half+0];
                if (r0 + 1 < RR) out[(size_t)q * RP + r0 + 1] = acc[ma][nb][2*half+1];
            }
        }
    }
}

// ============================================================
// energy[bh,q,k] = (QK + abs[h,q,k] + RS[bh,q,clip(k-q)+90]) / 8 ; mask
// Block 128x128, K=64, tf32 mma. 8 warps (warp 64x32).
// ============================================================
__global__ __launch_bounds__(256) void energy_tc(
    const float* __restrict__ abse, const int* __restrict__ mask)
{
    __shared__ float As[32][136];   // [d][q]
    __shared__ float Bs[32][136];   // [d][k]
    int kt = blockIdx.x, qt = blockIdx.y, bh = blockIdx.z;
    int q0 = qt * 128, k0 = kt * 128;
    const int tid = threadIdx.x, lane = tid & 31, wid = tid >> 5;
    const int gidq = lane >> 2, tig = lane & 3;
    const int warp_m = (wid & 1) * 64, warp_n = (wid >> 1) * 32;
    const int srow = tid & 31, scol = (tid >> 5) * 4;
    const float* Qb = g_Q + ((size_t)bh * Ss + q0) * Dd;
    const float* Kb = g_K + ((size_t)bh * Ss + k0) * Dd;

    float acc[4][4][4];
    #pragma unroll
    for (int i = 0; i < 4; i++)
        #pragma unroll
        for (int j = 0; j < 4; j++)
            #pragma unroll
            for (int r = 0; r < 4; r++) acc[i][j][r] = 0.f;

    for (int d0 = 0; d0 < 64; d0 += 32) {
        #pragma unroll
        for (int i = 0; i < 4; i++) {
            int ml = srow + 32 * i;
            float4 va = *(const float4*)(Qb + (size_t)ml * Dd + d0 + scol);
            As[scol+0][ml] = cvtf_tf32(va.x);
            As[scol+1][ml] = cvtf_tf32(va.y);
            As[scol+2][ml] = cvtf_tf32(va.z);
            As[scol+3][ml] = cvtf_tf32(va.w);
            float4 vb = *(const float4*)(Kb + (size_t)ml * Dd + d0 + scol);
            Bs[scol+0][ml] = cvtf_tf32(vb.x);
            Bs[scol+1][ml] = cvtf_tf32(vb.y);
            Bs[scol+2][ml] = cvtf_tf32(vb.z);
            Bs[scol+3][ml] = cvtf_tf32(vb.w);
        }
        __syncthreads();
        #pragma unroll
        for (int kk = 0; kk < 32; kk += 8) {
            uint32_t af[4][4], bf[4][2];
            #pragma unroll
            for (int ma = 0; ma < 4; ma++) {
                int m = warp_m + 16 * ma + gidq;
                af[ma][0] = __float_as_uint(As[kk+tig  ][m]);
                af[ma][1] = __float_as_uint(As[kk+tig  ][m+8]);
                af[ma][2] = __float_as_uint(As[kk+tig+4][m]);
                af[ma][3] = __float_as_uint(As[kk+tig+4][m+8]);
            }
            #pragma unroll
            for (int nb = 0; nb < 4; nb++) {
                int n = warp_n + 8 * nb + gidq;
                bf[nb][0] = __float_as_uint(Bs[kk+tig  ][n]);
                bf[nb][1] = __float_as_uint(Bs[kk+tig+4][n]);
            }
            #pragma unroll
            for (int ma = 0; ma < 4; ma++)
                #pragma unroll
                for (int nb = 0; nb < 4; nb++)
                    mma_tf32(acc[ma][nb], af[ma], bf[nb]);
        }
        __syncthreads();
    }

    int b = bh >> 4, h = bh & 15;
    const float* RSb = g_RS + (size_t)bh * Ss * RP;
    #pragma unroll
    for (int ma = 0; ma < 4; ma++) {
        int qm = q0 + warp_m + 16 * ma + gidq;
        #pragma unroll
        for (int half = 0; half < 2; half++) {
            int q = qm + 8 * half;
            #pragma unroll
            for (int nb = 0; nb < 4; nb++) {
                int k = k0 + warp_n + 8 * nb + 2 * tig;
                float2 av = *(const float2*)(abse + ((size_t)h * Ss + q) * Ss + k);
                int2 mv = *(const int2*)(mask + ((size_t)b * Ss + q) * Ss + k);
                int r0 = min(max(k     - q, -90), 90) + 90;
                int r1 = min(max(k + 1 - q, -90), 90) + 90;
                float e0 = (acc[ma][nb][2*half+0] + av.x + RSb[(size_t)q * RP + r0]) * 0.125f;
                float e1 = (acc[ma][nb][2*half+1] + av.y + RSb[(size_t)q * RP + r1]) * 0.125f;
                if (mv.x == 0) e0 = -1e10f;
                if (mv.y == 0) e1 = -1e10f;
                *(float2*)(g_P + ((size_t)bh * Ss + q) * Ss + k) = make_float2(e0, e1);
            }
        }
    }
}

// ============================================================
// softmax over last dim (1024) in place + fused bucket extraction:
// BS[bh,q,0]=sum_{k<=q-90}, BS[..,180]=sum_{k>=q+90}, BS[..,r]=attn[q,q+r-90]
// ============================================================
__global__ __launch_bounds__(256) void softmax_bk_kernel()
{
    __shared__ float redm[8];
    __shared__ float reds[8];
    __shared__ float rt0[8];
    __shared__ float rt1[8];
    int q = blockIdx.x, bh = blockIdx.y;
    float* p = g_P + ((size_t)bh * Ss + q) * Ss;
    float* out = g_BS + ((size_t)bh * Ss + q) * RP;
    int tid = threadIdx.x;
    float4 v = ((float4*)p)[tid];
    float m = fmaxf(fmaxf(v.x, v.y), fmaxf(v.z, v.w));
    #pragma unroll
    for (int o = 16; o; o >>= 1) m = fmaxf(m, __shfl_xor_sync(0xffffffffu, m, o));
    if ((tid & 31) == 0) redm[tid >> 5] = m;
    __syncthreads();
    m = redm[0];
    #pragma unroll
    for (int w = 1; w < 8; w++) m = fmaxf(m, redm[w]);
    float e[4];
    e[0] = __expf(v.x - m); e[1] = __expf(v.y - m);
    e[2] = __expf(v.z - m); e[3] = __expf(v.w - m);
    float s = e[0] + e[1] + e[2] + e[3];
    #pragma unroll
    for (int o = 16; o; o >>= 1) s += __shfl_xor_sync(0xffffffffu, s, o);
    if ((tid & 31) == 0) reds[tid >> 5] = s;
    __syncthreads();
    s = reds[0];
    #pragma unroll
    for (int w = 1; w < 8; w++) s += reds[w];
    float inv = 1.0f / s;
    float w0 = e[0]*inv, w1 = e[1]*inv, w2 = e[2]*inv, w3 = e[3]*inv;
    ((float4*)p)[tid] = make_float4(w0, w1, w2, w3);

    // zero-fill unreachable interior buckets (slots 1..179 with k out of range)
    if (tid >= 1 && tid <= 179) {
        int k = q + tid - 90;
        if (k < 0 || k >= Ss) out[tid] = 0.f;
    }
    // bucket extraction
    float t0 = 0.f, t1 = 0.f;
    float wv[4] = {w0, w1, w2, w3};
    #pragma unroll
    for (int j = 0; j < 4; j++) {
        int k = 4 * tid + j;
        int d = k - q;
        if (d <= -90) t0 += wv[j];
        else if (d >= 90) t1 += wv[j];
        else out[d + 90] = wv[j];
    }
    #pragma unroll
    for (int o = 16; o; o >>= 1) {
        t0 += __shfl_xor_sync(0xffffffffu, t0, o);
        t1 += __shfl_xor_sync(0xffffffffu, t1, o);
    }
    if ((tid & 31) == 0) { rt0[tid >> 5] = t0; rt1[tid >> 5] = t1; }
    __syncthreads();
    if (tid == 0) {
        float T0 = 0.f, T1 = 0.f;
        #pragma unroll
        for (int w = 0; w < 8; w++) { T0 += rt0[w]; T1 += rt1[w]; }
        out[0] = T0;
        out[180] = T1;
    }
}

// ============================================================
// x[b,q,h,d] = sum_k attn[bh,q,k] * V[bh,k,d]  (tf32 mma)
// Block: 128 q x 64 d, K-loop over 1024. 8 warps: warp 32x32 (2x4 atoms).
// ============================================================
__global__ __launch_bounds__(256) void xattn_tc()
{
    __shared__ float As[32][136];  // [k][q]  (P transposed)
    __shared__ float Vs[32][72];   // [k][d]
    int bh = blockIdx.y, q0 = blockIdx.x * 128;
    const int tid = threadIdx.x, lane = tid & 31, wid = tid >> 5;
    const int gidq = lane >> 2, tig = lane & 3;
    const int warp_m = (wid & 3) * 32, warp_n = (wid >> 2) * 32;
    const int srow = tid & 31, scol = (tid >> 5) * 4;
    const float* Pb = g_P + ((size_t)bh * Ss + q0) * Ss;
    const float* Vb = g_V + (size_t)bh * Ss * Dd;

    float acc[2][4][4];
    #pragma unroll
    for (int i = 0; i < 2; i++)
        #pragma unroll
        for (int j = 0; j < 4; j++)
            #pragma unroll
            for (int r = 0; r < 4; r++) acc[i][j][r] = 0.f;

    for (int k0 = 0; k0 < Ss; k0 += 32) {
        #pragma unroll
        for (int i = 0; i < 4; i++) {
            int ml = srow + 32 * i;
            float4 va = *(const float4*)(Pb + (size_t)ml * Ss + k0 + scol);
            As[scol+0][ml] = cvtf_tf32(va.x);
            As[scol+1][ml] = cvtf_tf32(va.y);
            As[scol+2][ml] = cvtf_tf32(va.z);
            As[scol+3][ml] = cvtf_tf32(va.w);
        }
        // V tile: rows k (32), cols d (64): tid -> col4=(tid&15)*4, row=(tid>>4)+16*i
        {
            int vc = (tid & 15) * 4;
            #pragma unroll
            for (int i = 0; i < 2; i++) {
                int kr = (tid >> 4) + 16 * i;
                float4 vv = *(const float4*)(Vb + (size_t)(k0 + kr) * Dd + vc);
                float4 o;
                o.x = cvtf_tf32(vv.x); o.y = cvtf_tf32(vv.y);
                o.z = cvtf_tf32(vv.z); o.w = cvtf_tf32(vv.w);
                *(float4*)&Vs[kr][vc] = o;
            }
        }
        __syncthreads();
        #pragma unroll
        for (int kk = 0; kk < 32; kk += 8) {
            uint32_t af[2][4], bf[4][2];
            #pragma unroll
            for (int ma = 0; ma < 2; ma++) {
                int mq = warp_m + 16 * ma + gidq;
                af[ma][0] = __float_as_uint(As[kk+tig  ][mq]);
                af[ma][1] = __float_as_uint(As[kk+tig  ][mq+8]);
                af[ma][2] = __float_as_uint(As[kk+tig+4][mq]);
                af[ma][3] = __float_as_uint(As[kk+tig+4][mq+8]);
            }
            #pragma unroll
            for (int nb = 0; nb < 4; nb++) {
                int n = warp_n + 8 * nb + gidq;
                bf[nb][0] = __float_as_uint(Vs[kk+tig  ][n]);
                bf[nb][1] = __float_as_uint(Vs[kk+tig+4][n]);
            }
            #pragma unroll
            for (int ma = 0; ma < 2; ma++)
                #pragma unroll
                for (int nb = 0; nb < 4; nb++)
                    mma_tf32(acc[ma][nb], af[ma], bf[nb]);
        }
        __syncthreads();
    }

    int b = bh >> 4, h = bh & 15;
    #pragma unroll
    for (int ma = 0; ma < 2; ma++) {
        int qm = q0 + warp_m + 16 * ma + gidq;
        #pragma unroll
        for (int nb = 0; nb < 4; nb++) {
            int d = warp_n + 8 * nb + 2 * tig;
            *(float2*)(g_X + ((size_t)(b*Ss + qm))     * HID + h*Dd + d) =
                make_float2(acc[ma][nb][0], acc[ma][nb][1]);
            *(float2*)(g_X + ((size_t)(b*Ss + qm + 8)) * HID + h*Dd + d) =
                make_float2(acc[ma][nb][2], acc[ma][nb][3]);
        }
    }
}

// ============================================================
// g_X[b,q,h,d] += BS[bh,q,:] @ rel_v_emb[:,d]
// ============================================================
__global__ __launch_bounds__(256) void rx_add_kernel(const float* __restrict__ rv)
{
    extern __shared__ float sm[];
    float (*BSs)[193] = (float(*)[193])sm;            // 64 x 193
    float (*rvs)[64]  = (float(*)[64])(sm + 64*193);  // 181 x 64
    int bh = blockIdx.y, q0 = blockIdx.x * 64;
    int tid = threadIdx.x, tx = tid & 15, ty = tid >> 4;
    const float* BSb = g_BS + ((size_t)bh * Ss + q0) * RP;
    for (int idx = tid; idx < 64*RP; idx += 256) {
        int q = idx / RP, r = idx % RP;
        BSs[q][r] = BSb[idx];
    }
    for (int idx = tid; idx < RR*64; idx += 256) {
        int r = idx >> 6, d = idx & 63;
        rvs[r][d] = rv[idx];
    }
    __syncthreads();
    float acc[4][4];
    #pragma unroll
    for (int i = 0; i < 4; i++)
        #pragma unroll
        for (int j = 0; j < 4; j++) acc[i][j] = 0.f;
    for (int r = 0; r < RR; r++) {
        float af[4], bf[4];
        #pragma unroll
        for (int i = 0; i < 4; i++) af[i] = BSs[ty + 16*i][r];
        #pragma unroll
        for (int j = 0; j < 4; j++) bf[j] = rvs[r][tx + 16*j];
        #pragma unroll
        for (int i = 0; i < 4; i++)
            #pragma unroll
            for (int j = 0; j < 4; j++)
                acc[i][j] += af[i] * bf[j];
    }
    int b = bh >> 4, h = bh & 15;
    #pragma unroll
    for (int i = 0; i < 4; i++) {
        int q = q0 + ty + 16*i;
        #pragma unroll
        for (int j = 0; j < 4; j++) {
            int d = tx + 16*j;
            size_t o = ((size_t)(b*Ss + q)) * HID + h*Dd + d;
            g_X[o] += acc[i][j];
        }
    }
}

// ============================================================
extern "C" void kernel_launch(void* const* d_in, const int* in_sizes, int n_in,
                              void* d_out, int out_size)
{
    const float* query = (const float*)d_in[0];
    const float* key   = (const float*)d_in[1];
    const float* value = (const float*)d_in[2];
    const int*   mask  = (const int*)  d_in[3];
    const float* abse  = (const float*)d_in[4];
    const float* Wq    = (const float*)d_in[5];
    const float* bq    = (const float*)d_in[6];
    const float* Wk    = (const float*)d_in[7];
    const float* bk    = (const float*)d_in[8];
    const float* Wv    = (const float*)d_in[9];
    const float* bv    = (const float*)d_in[10];
    const float* Wo    = (const float*)d_in[11];
    const float* bo    = (const float*)d_in[12];
    const float* rk    = (const float*)d_in[13];
    const float* rv    = (const float*)d_in[14];
    float* out = (float*)d_out;

    const int smem_rx = (64*193 + RR*64) * 4;
    cudaFuncSetAttribute(rx_add_kernel, cudaFuncAttributeMaxDynamicSharedMemorySize, smem_rx);

    dim3 gProj(HID/128, (Bb*Ss)/128);
    sgemm_bias_tc<<<gProj, 256>>>(query, Wq, bq, nullptr, 0, 0, 1);
    sgemm_bias_tc<<<gProj, 256>>>(key,   Wk, bk, nullptr, 0, 1, 1);
    sgemm_bias_tc<<<gProj, 256>>>(value, Wv, bv, nullptr, 0, 2, 1);

    rel_scores_tc<<<dim3(Ss/128, BH), 256>>>(rk);
    energy_tc<<<dim3(Ss/128, Ss/128, BH), 256>>>(abse, mask);
    softmax_bk_kernel<<<dim3(Ss, BH), 256>>>();
    xattn_tc<<<dim3(Ss/128, BH), 256>>>();
    rx_add_kernel<<<dim3(Ss/64, BH), 256, smem_rx>>>(rv);

    sgemm_bias_tc<<<gProj, 256>>>(nullptr, Wo, bo, out, 1, -1, 0);
}

// round 3
// speedup vs baseline: 1.8210x; 1.0010x over previous
#include <cuda_runtime.h>
#include <math.h>
#include <stdint.h>

// Problem constants
#define Bb   4
#define Ss   1024
#define Hh   16
#define Dd   64
#define HID  1024
#define BH   (Bb*Hh)       // 64
#define RR   181
#define RP   192           // padded bucket count

// -------- scratch (device globals; no runtime allocation) --------
__device__ float g_Q [(size_t)BH * Ss * Dd];
__device__ float g_K [(size_t)BH * Ss * Dd];
__device__ float g_V [(size_t)BH * Ss * Dd];
__device__ float g_RS[(size_t)BH * Ss * RP];
__device__ float g_BS[(size_t)BH * Ss * RP];
__device__ float g_P [(size_t)BH * Ss * Ss];
__device__ float g_X [(size_t)Bb * Ss * HID];

// ---------------- tf32 mma helpers ----------------
__device__ __forceinline__ uint32_t cvt_tf32(float x) {
    uint32_t r; asm("cvt.rna.tf32.f32 %0, %1;" : "=r"(r) : "f"(x)); return r;
}
__device__ __forceinline__ float cvtf_tf32(float x) {
    return __uint_as_float(cvt_tf32(x));
}
__device__ __forceinline__ void mma_tf32(float c[4], const uint32_t a[4], const uint32_t b[2]) {
    asm volatile(
        "mma.sync.aligned.m16n8k8.row.col.f32.tf32.tf32.f32 "
        "{%0,%1,%2,%3}, {%4,%5,%6,%7}, {%8,%9}, {%0,%1,%2,%3};"
        : "+f"(c[0]), "+f"(c[1]), "+f"(c[2]), "+f"(c[3])
        : "r"(a[0]), "r"(a[1]), "r"(a[2]), "r"(a[3]), "r"(b[0]), "r"(b[1]));
}

// ============================================================
// Tensor-core SGEMM: C[M,N] = A[M,K] @ W[N,K]^T + bias
// M=4096, N=K=1024. Block 128x128, BK=32, 8 warps (warp 64x32).
// out_mode 0: row-major [M,N]; out_mode 1: write [B,H,S,D]
// ============================================================
__global__ __launch_bounds__(256) void sgemm_bias_tc(
    const float* __restrict__ Ain, const float* __restrict__ W,
    const float* __restrict__ bias, float* __restrict__ Cout,
    int a_sel, int out_sel, int out_mode)
{
    const int K = HID, N = HID;
    __shared__ float As[32][136];   // [k][m], stride 136 (conflict-free frag loads)
    __shared__ float Bs[32][136];   // [k][n]
    const float* A = (a_sel == 1) ? g_X : Ain;
    float* C = (out_sel == 0) ? g_Q : (out_sel == 1) ? g_K : (out_sel == 2) ? g_V : Cout;

    const int tid = threadIdx.x, lane = tid & 31, wid = tid >> 5;
    const int gidq = lane >> 2, tig = lane & 3;
    const int warp_m = (wid & 1) * 64, warp_n = (wid >> 1) * 32;
    const int bm = blockIdx.y * 128, bn = blockIdx.x * 128;
    const int srow = tid & 31;
    const int scol = (tid >> 5) * 4;

    float acc[4][4][4];
    #pragma unroll
    for (int i = 0; i < 4; i++)
        #pragma unroll
        for (int j = 0; j < 4; j++)
            #pragma unroll
            for (int r = 0; r < 4; r++) acc[i][j][r] = 0.f;

    for (int k0 = 0; k0 < K; k0 += 32) {
        #pragma unroll
        for (int i = 0; i < 4; i++) {
            int ml = srow + 32 * i;
            float4 va = *(const float4*)(A + (size_t)(bm + ml) * K + k0 + scol);
            As[scol+0][ml] = cvtf_tf32(va.x);
            As[scol+1][ml] = cvtf_tf32(va.y);
            As[scol+2][ml] = cvtf_tf32(va.z);
            As[scol+3][ml] = cvtf_tf32(va.w);
            float4 vb = *(const float4*)(W + (size_t)(bn + ml) * K + k0 + scol);
            Bs[scol+0][ml] = cvtf_tf32(vb.x);
            Bs[scol+1][ml] = cvtf_tf32(vb.y);
            Bs[scol+2][ml] = cvtf_tf32(vb.z);
            Bs[scol+3][ml] = cvtf_tf32(vb.w);
        }
        __syncthreads();
        #pragma unroll
        for (int kk = 0; kk < 32; kk += 8) {
            uint32_t af[4][4], bf[4][2];
            #pragma unroll
            for (int ma = 0; ma < 4; ma++) {
                int m = warp_m + 16 * ma + gidq;
                af[ma][0] = __float_as_uint(As[kk+tig  ][m]);
                af[ma][1] = __float_as_uint(As[kk+tig  ][m+8]);
                af[ma][2] = __float_as_uint(As[kk+tig+4][m]);
                af[ma][3] = __float_as_uint(As[kk+tig+4][m+8]);
            }
            #pragma unroll
            for (int nb = 0; nb < 4; nb++) {
                int n = warp_n + 8 * nb + gidq;
                bf[nb][0] = __float_as_uint(Bs[kk+tig  ][n]);
                bf[nb][1] = __float_as_uint(Bs[kk+tig+4][n]);
            }
            #pragma unroll
            for (int ma = 0; ma < 4; ma++)
                #pragma unroll
                for (int nb = 0; nb < 4; nb++)
                    mma_tf32(acc[ma][nb], af[ma], bf[nb]);
        }
        __syncthreads();
    }

    #pragma unroll
    for (int ma = 0; ma < 4; ma++) {
        int m0 = bm + warp_m + 16 * ma + gidq;
        #pragma unroll
        for (int nb = 0; nb < 4; nb++) {
            int n0 = bn + warp_n + 8 * nb + 2 * tig;
            float bx = bias[n0], by = bias[n0 + 1];
            #pragma unroll
            for (int half = 0; half < 2; half++) {
                int m = m0 + 8 * half;
                float vx = acc[ma][nb][2*half+0] + bx;
                float vy = acc[ma][nb][2*half+1] + by;
                if (out_mode == 0) {
                    float2 o = make_float2(vx, vy);
                    *(float2*)(C + (size_t)m * N + n0) = o;
                } else {
                    int b = m >> 10, s = m & 1023, h = n0 >> 6, d = n0 & 63;
                    float2 o = make_float2(vx, vy);
                    *(float2*)(C + (((size_t)(b*Hh + h) * Ss) + s) * Dd + d) = o;
                }
            }
        }
    }
}

// ============================================================
// RS[bh,q,r] = sum_d Q[bh,q,d] * rel_k_emb[r,d]   (tf32 mma)
// Block: 128 q rows x 192 r cols, K=64 (2 chunks of 32).
// 8 warps: warp 64x48 (4 m-atoms x 6 n-atoms).
// ============================================================
__global__ __launch_bounds__(256) void rel_scores_tc(const float* __restrict__ rk)
{
    __shared__ float As[32][136];   // [k][q]
    __shared__ float Bs[32][200];   // [k][r]
    int bh = blockIdx.y, q0 = blockIdx.x * 128;
    const int tid = threadIdx.x, lane = tid & 31, wid = tid >> 5;
    const int gidq = lane >> 2, tig = lane & 3;
    const int warp_m = (wid & 1) * 64, warp_n = (wid >> 1) * 48;
    const int srow = tid & 31, scol = (tid >> 5) * 4;
    const float* Qb = g_Q + ((size_t)bh * Ss + q0) * Dd;

    float acc[4][6][4];
    #pragma unroll
    for (int i = 0; i < 4; i++)
        #pragma unroll
        for (int j = 0; j < 6; j++)
            #pragma unroll
            for (int r = 0; r < 4; r++) acc[i][j][r] = 0.f;

    for (int k0 = 0; k0 < 64; k0 += 32) {
        #pragma unroll
        for (int i = 0; i < 4; i++) {
            int ml = srow + 32 * i;
            float4 va = *(const float4*)(Qb + (size_t)ml * Dd + k0 + scol);
            As[scol+0][ml] = cvtf_tf32(va.x);
            As[scol+1][ml] = cvtf_tf32(va.y);
            As[scol+2][ml] = cvtf_tf32(va.z);
            As[scol+3][ml] = cvtf_tf32(va.w);
        }
        #pragma unroll
        for (int i = 0; i < 6; i++) {
            int rl = srow + 32 * i;
            float4 vb = (rl < RR) ? *(const float4*)(rk + (size_t)rl * Dd + k0 + scol)
                                  : make_float4(0.f, 0.f, 0.f, 0.f);
            Bs[scol+0][rl] = cvtf_tf32(vb.x);
            Bs[scol+1][rl] = cvtf_tf32(vb.y);
            Bs[scol+2][rl] = cvtf_tf32(vb.z);
            Bs[scol+3][rl] = cvtf_tf32(vb.w);
        }
        __syncthreads();
        #pragma unroll
        for (int kk = 0; kk < 32; kk += 8) {
            uint32_t af[4][4], bf[6][2];
            #pragma unroll
            for (int ma = 0; ma < 4; ma++) {
                int m = warp_m + 16 * ma + gidq;
                af[ma][0] = __float_as_uint(As[kk+tig  ][m]);
                af[ma][1] = __float_as_uint(As[kk+tig  ][m+8]);
                af[ma][2] = __float_as_uint(As[kk+tig+4][m]);
                af[ma][3] = __float_as_uint(As[kk+tig+4][m+8]);
            }
            #pragma unroll
            for (int nb = 0; nb < 6; nb++) {
                int n = warp_n + 8 * nb + gidq;
                bf[nb][0] = __float_as_uint(Bs[kk+tig  ][n]);
                bf[nb][1] = __float_as_uint(Bs[kk+tig+4][n]);
            }
            #pragma unroll
            for (int ma = 0; ma < 4; ma++)
                #pragma unroll
                for (int nb = 0; nb < 6; nb++)
                    mma_tf32(acc[ma][nb], af[ma], bf[nb]);
        }
        __syncthreads();
    }

    float* out = g_RS + ((size_t)bh * Ss + q0) * RP;
    #pragma unroll
    for (int ma = 0; ma < 4; ma++) {
        int qm = warp_m + 16 * ma + gidq;
        #pragma unroll
        for (int nb = 0; nb < 6; nb++) {
            int r0 = warp_n + 8 * nb + 2 * tig;
            #pragma unroll
            for (int half = 0; half < 2; half++) {
                int q = qm + 8 * half;
                if (r0 < RR)     out[(size_t)q * RP + r0]     = acc[ma][nb][2*half+0];
                if (r0 + 1 < RR) out[(size_t)q * RP + r0 + 1] = acc[ma][nb][2*half+1];
            }
        }
    }
}

// ============================================================
// energy[bh,q,k] = (QK + abs[h,q,k] + RS[bh,q,clip(k-q)+90]) / 8 ; mask
// Block 128x128, K=64, tf32 mma. 8 warps (warp 64x32).
// ============================================================
__global__ __launch_bounds__(256) void energy_tc(
    const float* __restrict__ abse, const int* __restrict__ mask)
{
    __shared__ float As[32][136];   // [d][q]
    __shared__ float Bs[32][136];   // [d][k]
    int kt = blockIdx.x, qt = blockIdx.y, bh = blockIdx.z;
    int q0 = qt * 128, k0 = kt * 128;
    const int tid = threadIdx.x, lane = tid & 31, wid = tid >> 5;
    const int gidq = lane >> 2, tig = lane & 3;
    const int warp_m = (wid & 1) * 64, warp_n = (wid >> 1) * 32;
    const int srow = tid & 31, scol = (tid >> 5) * 4;
    const float* Qb = g_Q + ((size_t)bh * Ss + q0) * Dd;
    const float* Kb = g_K + ((size_t)bh * Ss + k0) * Dd;

    float acc[4][4][4];
    #pragma unroll
    for (int i = 0; i < 4; i++)
        #pragma unroll
        for (int j = 0; j < 4; j++)
            #pragma unroll
            for (int r = 0; r < 4; r++) acc[i][j][r] = 0.f;

    for (int d0 = 0; d0 < 64; d0 += 32) {
        #pragma unroll
        for (int i = 0; i < 4; i++) {
            int ml = srow + 32 * i;
            float4 va = *(const float4*)(Qb + (size_t)ml * Dd + d0 + scol);
            As[scol+0][ml] = cvtf_tf32(va.x);
            As[scol+1][ml] = cvtf_tf32(va.y);
            As[scol+2][ml] = cvtf_tf32(va.z);
            As[scol+3][ml] = cvtf_tf32(va.w);
            float4 vb = *(const float4*)(Kb + (size_t)ml * Dd + d0 + scol);
            Bs[scol+0][ml] = cvtf_tf32(vb.x);
            Bs[scol+1][ml] = cvtf_tf32(vb.y);
            Bs[scol+2][ml] = cvtf_tf32(vb.z);
            Bs[scol+3][ml] = cvtf_tf32(vb.w);
        }
        __syncthreads();
        #pragma unroll
        for (int kk = 0; kk < 32; kk += 8) {
            uint32_t af[4][4], bf[4][2];
            #pragma unroll
            for (int ma = 0; ma < 4; ma++) {
                int m = warp_m + 16 * ma + gidq;
                af[ma][0] = __float_as_uint(As[kk+tig  ][m]);
                af[ma][1] = __float_as_uint(As[kk+tig  ][m+8]);
                af[ma][2] = __float_as_uint(As[kk+tig+4][m]);
                af[ma][3] = __float_as_uint(As[kk+tig+4][m+8]);
            }
            #pragma unroll
            for (int nb = 0; nb < 4; nb++) {
                int n = warp_n + 8 * nb + gidq;
                bf[nb][0] = __float_as_uint(Bs[kk+tig  ][n]);
                bf[nb][1] = __float_as_uint(Bs[kk+tig+4][n]);
            }
            #pragma unroll
            for (int ma = 0; ma < 4; ma++)
                #pragma unroll
                for (int nb = 0; nb < 4; nb++)
                    mma_tf32(acc[ma][nb], af[ma], bf[nb]);
        }
        __syncthreads();
    }

    int b = bh >> 4, h = bh & 15;
    const float* RSb = g_RS + (size_t)bh * Ss * RP;
    #pragma unroll
    for (int ma = 0; ma < 4; ma++) {
        int qm = q0 + warp_m + 16 * ma + gidq;
        #pragma unroll
        for (int half = 0; half < 2; half++) {
            int q = qm + 8 * half;
            #pragma unroll
            for (int nb = 0; nb < 4; nb++) {
                int k = k0 + warp_n + 8 * nb + 2 * tig;
                float2 av = *(const float2*)(abse + ((size_t)h * Ss + q) * Ss + k);
                int2 mv = *(const int2*)(mask + ((size_t)b * Ss + q) * Ss + k);
                int r0 = min(max(k     - q, -90), 90) + 90;
                int r1 = min(max(k + 1 - q, -90), 90) + 90;
                float e0 = (acc[ma][nb][2*half+0] + av.x + RSb[(size_t)q * RP + r0]) * 0.125f;
                float e1 = (acc[ma][nb][2*half+1] + av.y + RSb[(size_t)q * RP + r1]) * 0.125f;
                if (mv.x == 0) e0 = -1e10f;
                if (mv.y == 0) e1 = -1e10f;
                *(float2*)(g_P + ((size_t)bh * Ss + q) * Ss + k) = make_float2(e0, e1);
            }
        }
    }
}

// ============================================================
// softmax over last dim (1024) in place + fused bucket extraction:
// BS[bh,q,0]=sum_{k<=q-90}, BS[..,180]=sum_{k>=q+90}, BS[..,r]=attn[q,q+r-90]
// ============================================================
__global__ __launch_bounds__(256) void softmax_bk_kernel()
{
    __shared__ float redm[8];
    __shared__ float reds[8];
    __shared__ float rt0[8];
    __shared__ float rt1[8];
    int q = blockIdx.x, bh = blockIdx.y;
    float* p = g_P + ((size_t)bh * Ss + q) * Ss;
    float* out = g_BS + ((size_t)bh * Ss + q) * RP;
    int tid = threadIdx.x;
    float4 v = ((float4*)p)[tid];
    float m = fmaxf(fmaxf(v.x, v.y), fmaxf(v.z, v.w));
    #pragma unroll
    for (int o = 16; o; o >>= 1) m = fmaxf(m, __shfl_xor_sync(0xffffffffu, m, o));
    if ((tid & 31) == 0) redm[tid >> 5] = m;
    __syncthreads();
    m = redm[0];
    #pragma unroll
    for (int w = 1; w < 8; w++) m = fmaxf(m, redm[w]);
    float e[4];
    e[0] = __expf(v.x - m); e[1] = __expf(v.y - m);
    e[2] = __expf(v.z - m); e[3] = __expf(v.w - m);
    float s = e[0] + e[1] + e[2] + e[3];
    #pragma unroll
    for (int o = 16; o; o >>= 1) s += __shfl_xor_sync(0xffffffffu, s, o);
    if ((tid & 31) == 0) reds[tid >> 5] = s;
    __syncthreads();
    s = reds[0];
    #pragma unroll
    for (int w = 1; w < 8; w++) s += reds[w];
    float inv = 1.0f / s;
    float w0 = e[0]*inv, w1 = e[1]*inv, w2 = e[2]*inv, w3 = e[3]*inv;
    ((float4*)p)[tid] = make_float4(w0, w1, w2, w3);

    // zero-fill unreachable interior buckets (slots 1..179 with k out of range)
    if (tid >= 1 && tid <= 179) {
        int k = q + tid - 90;
        if (k < 0 || k >= Ss) out[tid] = 0.f;
    }
    // bucket extraction
    float t0 = 0.f, t1 = 0.f;
    float wv[4] = {w0, w1, w2, w3};
    #pragma unroll
    for (int j = 0; j < 4; j++) {
        int k = 4 * tid + j;
        int d = k - q;
        if (d <= -90) t0 += wv[j];
        else if (d >= 90) t1 += wv[j];
        else out[d + 90] = wv[j];
    }
    #pragma unroll
    for (int o = 16; o; o >>= 1) {
        t0 += __shfl_xor_sync(0xffffffffu, t0, o);
        t1 += __shfl_xor_sync(0xffffffffu, t1, o);
    }
    if ((tid & 31) == 0) { rt0[tid >> 5] = t0; rt1[tid >> 5] = t1; }
    __syncthreads();
    if (tid == 0) {
        float T0 = 0.f, T1 = 0.f;
        #pragma unroll
        for (int w = 0; w < 8; w++) { T0 += rt0[w]; T1 += rt1[w]; }
        out[0] = T0;
        out[180] = T1;
    }
}

// ============================================================
// x[b,q,h,d] = sum_k attn[bh,q,k] * V[bh,k,d]  (tf32 mma)
// Block: 128 q x 64 d, K-loop over 1024. 8 warps: warp 32x32 (2x4 atoms).
// ============================================================
__global__ __launch_bounds__(256) void xattn_tc()
{
    __shared__ float As[32][136];  // [k][q]  (P transposed)
    __shared__ float Vs[32][72];   // [k][d]
    int bh = blockIdx.y, q0 = blockIdx.x * 128;
    const int tid = threadIdx.x, lane = tid & 31, wid = tid >> 5;
    const int gidq = lane >> 2, tig = lane & 3;
    const int warp_m = (wid & 3) * 32, warp_n = (wid >> 2) * 32;
    const int srow = tid & 31, scol = (tid >> 5) * 4;
    const float* Pb = g_P + ((size_t)bh * Ss + q0) * Ss;
    const float* Vb = g_V + (size_t)bh * Ss * Dd;

    float acc[2][4][4];
    #pragma unroll
    for (int i = 0; i < 2; i++)
        #pragma unroll
        for (int j = 0; j < 4; j++)
            #pragma unroll
            for (int r = 0; r < 4; r++) acc[i][j][r] = 0.f;

    for (int k0 = 0; k0 < Ss; k0 += 32) {
        #pragma unroll
        for (int i = 0; i < 4; i++) {
            int ml = srow + 32 * i;
            float4 va = *(const float4*)(Pb + (size_t)ml * Ss + k0 + scol);
            As[scol+0][ml] = cvtf_tf32(va.x);
            As[scol+1][ml] = cvtf_tf32(va.y);
            As[scol+2][ml] = cvtf_tf32(va.z);
            As[scol+3][ml] = cvtf_tf32(va.w);
        }
        // V tile: rows k (32), cols d (64): tid -> col4=(tid&15)*4, row=(tid>>4)+16*i
        {
            int vc = (tid & 15) * 4;
            #pragma unroll
            for (int i = 0; i < 2; i++) {
                int kr = (tid >> 4) + 16 * i;
                float4 vv = *(const float4*)(Vb + (size_t)(k0 + kr) * Dd + vc);
                float4 o;
                o.x = cvtf_tf32(vv.x); o.y = cvtf_tf32(vv.y);
                o.z = cvtf_tf32(vv.z); o.w = cvtf_tf32(vv.w);
                *(float4*)&Vs[kr][vc] = o;
            }
        }
        __syncthreads();
        #pragma unroll
        for (int kk = 0; kk < 32; kk += 8) {
            uint32_t af[2][4], bf[4][2];
            #pragma unroll
            for (int ma = 0; ma < 2; ma++) {
                int mq = warp_m + 16 * ma + gidq;
                af[ma][0] = __float_as_uint(As[kk+tig  ][mq]);
                af[ma][1] = __float_as_uint(As[kk+tig  ][mq+8]);
                af[ma][2] = __float_as_uint(As[kk+tig+4][mq]);
                af[ma][3] = __float_as_uint(As[kk+tig+4][mq+8]);
            }
            #pragma unroll
            for (int nb = 0; nb < 4; nb++) {
                int n = warp_n + 8 * nb + gidq;
                bf[nb][0] = __float_as_uint(Vs[kk+tig  ][n]);
                bf[nb][1] = __float_as_uint(Vs[kk+tig+4][n]);
            }
            #pragma unroll
            for (int ma = 0; ma < 2; ma++)
                #pragma unroll
                for (int nb = 0; nb < 4; nb++)
                    mma_tf32(acc[ma][nb], af[ma], bf[nb]);
        }
        __syncthreads();
    }

    int b = bh >> 4, h = bh & 15;
    #pragma unroll
    for (int ma = 0; ma < 2; ma++) {
        int qm = q0 + warp_m + 16 * ma + gidq;
        #pragma unroll
        for (int nb = 0; nb < 4; nb++) {
            int d = warp_n + 8 * nb + 2 * tig;
            *(float2*)(g_X + ((size_t)(b*Ss + qm))     * HID + h*Dd + d) =
                make_float2(acc[ma][nb][0], acc[ma][nb][1]);
            *(float2*)(g_X + ((size_t)(b*Ss + qm + 8)) * HID + h*Dd + d) =
                make_float2(acc[ma][nb][2], acc[ma][nb][3]);
        }
    }
}

// ============================================================
// g_X[b,q,h,d] += BS[bh,q,:] @ rel_v_emb[:,d]
// ============================================================
__global__ __launch_bounds__(256) void rx_add_kernel(const float* __restrict__ rv)
{
    extern __shared__ float sm[];
    float (*BSs)[193] = (float(*)[193])sm;            // 64 x 193
    float (*rvs)[64]  = (float(*)[64])(sm + 64*193);  // 181 x 64
    int bh = blockIdx.y, q0 = blockIdx.x * 64;
    int tid = threadIdx.x, tx = tid & 15, ty = tid >> 4;
    const float* BSb = g_BS + ((size_t)bh * Ss + q0) * RP;
    for (int idx = tid; idx < 64*RP; idx += 256) {
        int q = idx / RP, r = idx % RP;
        BSs[q][r] = BSb[idx];
    }
    for (int idx = tid; idx < RR*64; idx += 256) {
        int r = idx >> 6, d = idx & 63;
        rvs[r][d] = rv[idx];
    }
    __syncthreads();
    float acc[4][4];
    #pragma unroll
    for (int i = 0; i < 4; i++)
        #pragma unroll
        for (int j = 0; j < 4; j++) acc[i][j] = 0.f;
    for (int r = 0; r < RR; r++) {
        float af[4], bf[4];
        #pragma unroll
        for (int i = 0; i < 4; i++) af[i] = BSs[ty + 16*i][r];
        #pragma unroll
        for (int j = 0; j < 4; j++) bf[j] = rvs[r][tx + 16*j];
        #pragma unroll
        for (int i = 0; i < 4; i++)
            #pragma unroll
            for (int j = 0; j < 4; j++)
                acc[i][j] += af[i] * bf[j];
    }
    int b = bh >> 4, h = bh & 15;
    #pragma unroll
    for (int i = 0; i < 4; i++) {
        int q = q0 + ty + 16*i;
        #pragma unroll
        for (int j = 0; j < 4; j++) {
            int d = tx + 16*j;
            size_t o = ((size_t)(b*Ss + q)) * HID + h*Dd + d;
            g_X[o] += acc[i][j];
        }
    }
}

// ============================================================
extern "C" void kernel_launch(void* const* d_in, const int* in_sizes, int n_in,
                              void* d_out, int out_size)
{
    const float* query = (const float*)d_in[0];
    const float* key   = (const float*)d_in[1];
    const float* value = (const float*)d_in[2];
    const int*   mask  = (const int*)  d_in[3];
    const float* abse  = (const float*)d_in[4];
    const float* Wq    = (const float*)d_in[5];
    const float* bq    = (const float*)d_in[6];
    const float* Wk    = (const float*)d_in[7];
    const float* bk    = (const float*)d_in[8];
    const float* Wv    = (const float*)d_in[9];
    const float* bv    = (const float*)d_in[10];
    const float* Wo    = (const float*)d_in[11];
    const float* bo    = (const float*)d_in[12];
    const float* rk    = (const float*)d_in[13];
    const float* rv    = (const float*)d_in[14];
    float* out = (float*)d_out;

    const int smem_rx = (64*193 + RR*64) * 4;
    cudaFuncSetAttribute(rx_add_kernel, cudaFuncAttributeMaxDynamicSharedMemorySize, smem_rx);

    dim3 gProj(HID/128, (Bb*Ss)/128);
    sgemm_bias_tc<<<gProj, 256>>>(query, Wq, bq, nullptr, 0, 0, 1);
    sgemm_bias_tc<<<gProj, 256>>>(key,   Wk, bk, nullptr, 0, 1, 1);
    sgemm_bias_tc<<<gProj, 256>>>(value, Wv, bv, nullptr, 0, 2, 1);

    rel_scores_tc<<<dim3(Ss/128, BH), 256>>>(rk);
    energy_tc<<<dim3(Ss/128, Ss/128, BH), 256>>>(abse, mask);
    softmax_bk_kernel<<<dim3(Ss, BH), 256>>>();
    xattn_tc<<<dim3(Ss/128, BH), 256>>>();
    rx_add_kernel<<<dim3(Ss/64, BH), 256, smem_rx>>>(rv);

    sgemm_bias_tc<<<gProj, 256>>>(nullptr, Wo, bo, out, 1, -1, 0);
}